// round 3
// baseline (speedup 1.0000x reference)
#include <cuda_runtime.h>

#define BB     2048
#define NCTX   64
#define ZD     64
#define RD     128
#define HD     128
#define NSTEPS 20
#define DT     0.05f
#define DIFF   0.3162277660168379f   /* sqrt(2*dt) */

// scratch (device globals: no allocations allowed)
__device__ float g_r[BB * RD];      // encoder output r
__device__ float g_grad[BB * ZD];   // clipped energy gradient per step

__device__ __forceinline__ float sigf(float x) { return 1.0f / (1.0f + __expf(-x)); }

// ---------------------------------------------------------------------------
// Encoder: r[b] = sum_n silu(silu([x,y]We1+b)We2+b)We3+b * m / max(sum m,1e-6)
// One block <-> strided b's. We2/We3 in SMEM (forward-only: stride 128 is
// conflict-free for fixed-k, varying-tid access). 4 context points / iter.
// ---------------------------------------------------------------------------
__global__ void __launch_bounds__(128, 1) encoder_kernel(
    const float* __restrict__ x_ctx, const float* __restrict__ y_ctx,
    const float* __restrict__ mask,
    const float* __restrict__ We1, const float* __restrict__ be1,
    const float* __restrict__ We2, const float* __restrict__ be2,
    const float* __restrict__ We3, const float* __restrict__ be3)
{
    extern __shared__ float sm[];
    float4* h1s  = (float4*)sm;           // 128 float4
    float4* h2s  = h1s + 128;             // 128 float4
    float*  We2s = (float*)(h2s + 128);   // 128*128
    float*  We3s = We2s + HD * HD;        // 128*128
    float*  xs   = We3s + HD * HD;        // 128
    float*  ys   = xs + 128;              // 64
    float*  ms   = ys + 64;               // 64

    const int tid = threadIdx.x;
    for (int i = tid; i < HD * HD; i += 128) { We2s[i] = We2[i]; We3s[i] = We3[i]; }
    const float w10 = We1[tid], w11 = We1[HD + tid], w12 = We1[2 * HD + tid];
    const float b1 = be1[tid], b2 = be2[tid], b3 = be3[tid];
    __syncthreads();

    for (int b = blockIdx.x; b < BB; b += gridDim.x) {
        xs[tid] = x_ctx[b * (NCTX * 2) + tid];
        if (tid < NCTX) { ys[tid] = y_ctx[b * NCTX + tid]; ms[tid] = mask[b * NCTX + tid]; }
        __syncthreads();

        float racc = 0.0f;
        #pragma unroll 1
        for (int it = 0; it < NCTX / 4; ++it) {
            const int n0 = it * 4;
            float4 h1;
            float* hp = (float*)&h1;
            #pragma unroll
            for (int q = 0; q < 4; ++q) {
                const int n = n0 + q;
                float p = b1 + xs[2 * n] * w10 + xs[2 * n + 1] * w11 + ys[n] * w12;
                hp[q] = p * sigf(p);
            }
            h1s[tid] = h1;
            __syncthreads();

            float a0 = b2, a1 = b2, a2 = b2, a3 = b2;
            #pragma unroll 8
            for (int k = 0; k < HD; ++k) {
                float4 hh = h1s[k];
                float  w  = We2s[k * HD + tid];
                a0 = fmaf(hh.x, w, a0); a1 = fmaf(hh.y, w, a1);
                a2 = fmaf(hh.z, w, a2); a3 = fmaf(hh.w, w, a3);
            }
            float4 h2;
            h2.x = a0 * sigf(a0); h2.y = a1 * sigf(a1);
            h2.z = a2 * sigf(a2); h2.w = a3 * sigf(a3);
            h2s[tid] = h2;
            __syncthreads();

            a0 = b3; a1 = b3; a2 = b3; a3 = b3;
            #pragma unroll 8
            for (int k = 0; k < HD; ++k) {
                float4 hh = h2s[k];
                float  w  = We3s[k * HD + tid];
                a0 = fmaf(hh.x, w, a0); a1 = fmaf(hh.y, w, a1);
                a2 = fmaf(hh.z, w, a2); a3 = fmaf(hh.w, w, a3);
            }
            racc = fmaf(a0, ms[n0 + 0], racc);
            racc = fmaf(a1, ms[n0 + 1], racc);
            racc = fmaf(a2, ms[n0 + 2], racc);
            racc = fmaf(a3, ms[n0 + 3], racc);
        }
        float msum = 0.0f;
        #pragma unroll
        for (int n = 0; n < NCTX; ++n) msum += ms[n];
        g_r[b * RD + tid] = racc / fmaxf(msum, 1e-6f);
        __syncthreads();
    }
}

// ---------------------------------------------------------------------------
// Energy-gradient kernel: g[b] = clip(z + t * d(u_lik)/dz, +-100).
// Decoder fwd+bwd over 64 ctx points, 4 per iteration.
// Wd1/Wd2 padded to stride 129 -> conflict-free for BOTH W (fwd, fixed k)
// and W^T (bwd, fixed col) access. dz deferred: accumulate sum_n dpre1 in
// registers, single W1^T matvec at the end. z-part of pre1 hoisted out of n.
// ---------------------------------------------------------------------------
__global__ void __launch_bounds__(128, 2) grad_kernel(
    const float* __restrict__ z, const float* __restrict__ x_ctx,
    const float* __restrict__ y_ctx, const float* __restrict__ mask,
    const float* __restrict__ Wd1, const float* __restrict__ bd1,
    const float* __restrict__ Wd2, const float* __restrict__ bd2,
    const float* __restrict__ Wd3, const float* __restrict__ bd3,
    float t)
{
    extern __shared__ float sm[];
    float4* h1s  = (float4*)sm;            // 128 float4 (h1 for 4 ctx pts)
    float4* dps  = h1s + 128;              // 128 float4 (dpre2 for 4 ctx pts)
    float4* wsum = dps + 128;              // 4 float4 (cross-warp reduce)
    float*  Wd1p = (float*)(wsum + 4);     // 66*129
    float*  Wd2p = Wd1p + 66 * 129;        // 128*129
    float*  xs   = Wd2p + 128 * 129;       // 128
    float*  ys   = xs + 128;               // 64
    float*  ms   = ys + 64;                // 64
    float*  zsh  = ms + 64;                // 64
    float*  ds   = zsh + 64;               // 128 (sum_n dpre1)

    const int tid = threadIdx.x;
    for (int i = tid; i < 66 * HD; i += 128) {
        int r = i >> 7, c = i & 127;
        Wd1p[r * 129 + c] = Wd1[i];
    }
    for (int i = tid; i < HD * HD; i += 128) {
        int r = i >> 7, c = i & 127;
        Wd2p[r * 129 + c] = Wd2[i];
    }
    const float b1 = bd1[tid], b2 = bd2[tid], w3 = Wd3[tid], bd3v = bd3[0];
    __syncthreads();
    const float wx0 = Wd1p[64 * 129 + tid];   // x-feature rows of Wd1
    const float wx1 = Wd1p[65 * 129 + tid];

    for (int b = blockIdx.x; b < BB; b += gridDim.x) {
        if (tid < ZD) zsh[tid] = z[b * ZD + tid];
        xs[tid] = x_ctx[b * (NCTX * 2) + tid];
        if (tid < NCTX) { ys[tid] = y_ctx[b * NCTX + tid]; ms[tid] = mask[b * NCTX + tid]; }
        __syncthreads();

        // n-invariant part of layer-1 preactivation (z contribution + bias)
        float pre1b = b1;
        #pragma unroll 8
        for (int k = 0; k < ZD; ++k) pre1b = fmaf(zsh[k], Wd1p[k * 129 + tid], pre1b);

        float dpsum = 0.0f;   // sum over n of dpre1[tid]
        if (t > 0.0f) {
            #pragma unroll 1
            for (int it = 0; it < NCTX / 4; ++it) {
                const int n0 = it * 4;
                float sd1[4];
                float4 h1;
                float* hp = (float*)&h1;
                #pragma unroll
                for (int q = 0; q < 4; ++q) {
                    const int n = n0 + q;
                    float p = fmaf(xs[2 * n], wx0, fmaf(xs[2 * n + 1], wx1, pre1b));
                    float s = sigf(p);
                    hp[q]  = p * s;
                    sd1[q] = s * (1.0f + p * (1.0f - s));   // silu'(pre1)
                }
                h1s[tid] = h1;
                __syncthreads();                              // A

                float a0 = b2, a1 = b2, a2 = b2, a3 = b2;
                #pragma unroll 8
                for (int k = 0; k < HD; ++k) {
                    float4 hh = h1s[k];
                    float  w  = Wd2p[k * 129 + tid];
                    a0 = fmaf(hh.x, w, a0); a1 = fmaf(hh.y, w, a1);
                    a2 = fmaf(hh.z, w, a2); a3 = fmaf(hh.w, w, a3);
                }
                const float s0 = sigf(a0), s1 = sigf(a1), s2 = sigf(a2), s3 = sigf(a3);
                float4 part;
                part.x = a0 * s0 * w3; part.y = a1 * s1 * w3;
                part.z = a2 * s2 * w3; part.w = a3 * s3 * w3;
                const float t0 = s0 * (1.0f + a0 * (1.0f - s0));  // silu'(pre2)
                const float t1 = s1 * (1.0f + a1 * (1.0f - s1));
                const float t2 = s2 * (1.0f + a2 * (1.0f - s2));
                const float t3 = s3 * (1.0f + a3 * (1.0f - s3));

                #pragma unroll
                for (int off = 16; off; off >>= 1) {
                    part.x += __shfl_xor_sync(0xffffffffu, part.x, off);
                    part.y += __shfl_xor_sync(0xffffffffu, part.y, off);
                    part.z += __shfl_xor_sync(0xffffffffu, part.z, off);
                    part.w += __shfl_xor_sync(0xffffffffu, part.w, off);
                }
                if ((tid & 31) == 0) wsum[tid >> 5] = part;
                __syncthreads();                              // B

                float4 r0 = wsum[0], r1 = wsum[1], r2 = wsum[2], r3 = wsum[3];
                const float out0 = r0.x + r1.x + r2.x + r3.x + bd3v;
                const float out1 = r0.y + r1.y + r2.y + r3.y + bd3v;
                const float out2 = r0.z + r1.z + r2.z + r3.z + bd3v;
                const float out3 = r0.w + r1.w + r2.w + r3.w + bd3v;
                // dU/d(out) = -t*(y-out)*m ; dpre2 = dU/dout * Wd3[j] * silu'(pre2)
                float4 dp;
                dp.x = -t * (ys[n0 + 0] - out0) * ms[n0 + 0] * w3 * t0;
                dp.y = -t * (ys[n0 + 1] - out1) * ms[n0 + 1] * w3 * t1;
                dp.z = -t * (ys[n0 + 2] - out2) * ms[n0 + 2] * w3 * t2;
                dp.w = -t * (ys[n0 + 3] - out3) * ms[n0 + 3] * w3 * t3;
                dps[tid] = dp;
                __syncthreads();                              // C

                float c0 = 0.0f, c1 = 0.0f, c2 = 0.0f, c3 = 0.0f;
                #pragma unroll 8
                for (int k = 0; k < HD; ++k) {
                    float4 dd = dps[k];
                    float  w  = Wd2p[tid * 129 + k];          // Wd2^T row, conflict-free
                    c0 = fmaf(dd.x, w, c0); c1 = fmaf(dd.y, w, c1);
                    c2 = fmaf(dd.z, w, c2); c3 = fmaf(dd.w, w, c3);
                }
                dpsum += c0 * sd1[0] + c1 * sd1[1] + c2 * sd1[2] + c3 * sd1[3];
            }
        }
        __syncthreads();
        ds[tid] = dpsum;
        __syncthreads();
        if (tid < ZD) {
            float acc = 0.0f;
            #pragma unroll 8
            for (int j = 0; j < HD; ++j) acc = fmaf(ds[j], Wd1p[tid * 129 + j], acc);
            float g = zsh[tid] + acc;                         // + u_prior grad (= z)
            g = fminf(fmaxf(g, -100.0f), 100.0f);
            g_grad[b * ZD + tid] = g;
        }
        __syncthreads();
    }
}

// ---------------------------------------------------------------------------
// Drift + z update: b = MLP([z, r, t]); z <- z + (b - g)*dt + diff*noise
// Drift weights (192 KB) in SMEM, one CTA/SM, ~14 b's per block.
// ---------------------------------------------------------------------------
__global__ void __launch_bounds__(128, 1) drift_kernel(
    float* __restrict__ z, const float* __restrict__ noise,
    const float* __restrict__ Wf1, const float* __restrict__ bf1,
    const float* __restrict__ Wf2, const float* __restrict__ bf2,
    const float* __restrict__ Wf3, const float* __restrict__ bf3,
    float t)
{
    extern __shared__ float sm[];
    float* Wf1s = sm;                      // 193*128
    float* Wf2s = Wf1s + 193 * HD;         // 128*128
    float* Wf3s = Wf2s + HD * HD;          // 128*64
    float* f1s  = Wf3s + HD * ZD;          // 128
    float* f2s  = f1s + 128;               // 128
    float* zsh  = f2s + 128;               // 64
    float* rsh  = zsh + 64;                // 128
    float* psum = rsh + 128;               // 128

    const int tid = threadIdx.x;
    for (int i = tid; i < 193 * HD; i += 128) Wf1s[i] = Wf1[i];
    for (int i = tid; i < HD * HD; i += 128)  Wf2s[i] = Wf2[i];
    for (int i = tid; i < HD * ZD; i += 128)  Wf3s[i] = Wf3[i];
    const float b1 = bf1[tid], b2 = bf2[tid];
    __syncthreads();
    const float wt = Wf1s[192 * HD + tid];

    for (int b = blockIdx.x; b < BB; b += gridDim.x) {
        if (tid < ZD) zsh[tid] = z[b * ZD + tid];
        rsh[tid] = g_r[b * RD + tid];
        __syncthreads();

        float p = fmaf(t, wt, b1);
        #pragma unroll 8
        for (int k = 0; k < ZD; ++k) p = fmaf(zsh[k], Wf1s[k * HD + tid], p);
        #pragma unroll 8
        for (int k = 0; k < RD; ++k) p = fmaf(rsh[k], Wf1s[(ZD + k) * HD + tid], p);
        f1s[tid] = p * sigf(p);
        __syncthreads();

        float p2 = b2;
        #pragma unroll 8
        for (int k = 0; k < HD; ++k) p2 = fmaf(f1s[k], Wf2s[k * HD + tid], p2);
        f2s[tid] = p2 * sigf(p2);
        __syncthreads();

        const int kk = tid & 63, half = tid >> 6;
        float acc = 0.0f;
        #pragma unroll 8
        for (int j = 0; j < 64; ++j)
            acc = fmaf(f2s[half * 64 + j], Wf3s[(half * 64 + j) * ZD + kk], acc);
        psum[tid] = acc;
        __syncthreads();

        if (tid < ZD) {
            const float bdrift = bf3[tid] + psum[tid] + psum[tid + 64];
            const float zn = zsh[tid] + (bdrift - g_grad[b * ZD + tid]) * DT
                           + DIFF * noise[b * ZD + tid];
            z[b * ZD + tid] = zn;
        }
        __syncthreads();
    }
}

// ---------------------------------------------------------------------------
extern "C" void kernel_launch(void* const* d_in, const int* in_sizes, int n_in,
                              void* d_out, int out_size)
{
    const float* x_ctx  = (const float*)d_in[0];
    const float* y_ctx  = (const float*)d_in[1];
    const float* mask   = (const float*)d_in[2];
    const float* z0     = (const float*)d_in[3];
    const float* noises = (const float*)d_in[4];
    const float* We1 = (const float*)d_in[5];  const float* be1 = (const float*)d_in[6];
    const float* We2 = (const float*)d_in[7];  const float* be2 = (const float*)d_in[8];
    const float* We3 = (const float*)d_in[9];  const float* be3 = (const float*)d_in[10];
    const float* Wd1 = (const float*)d_in[11]; const float* bd1 = (const float*)d_in[12];
    const float* Wd2 = (const float*)d_in[13]; const float* bd2 = (const float*)d_in[14];
    const float* Wd3 = (const float*)d_in[15]; const float* bd3 = (const float*)d_in[16];
    const float* Wf1 = (const float*)d_in[17]; const float* bf1 = (const float*)d_in[18];
    const float* Wf2 = (const float*)d_in[19]; const float* bf2 = (const float*)d_in[20];
    const float* Wf3 = (const float*)d_in[21]; const float* bf3 = (const float*)d_in[22];
    float* z = (float*)d_out;   // z buffer lives in d_out; final state is the answer

    const size_t smE = (size_t)(512 + 512 + 16384 + 16384 + 128 + 64 + 64) * 4;
    const size_t smG = (size_t)(512 + 512 + 16 + 66 * 129 + 128 * 129
                                + 128 + 64 + 64 + 64 + 128) * 4;
    const size_t smF = (size_t)(193 * 128 + 128 * 128 + 128 * 64
                                + 128 + 128 + 64 + 128 + 128) * 4;

    cudaFuncSetAttribute(encoder_kernel, cudaFuncAttributeMaxDynamicSharedMemorySize, (int)smE);
    cudaFuncSetAttribute(grad_kernel,    cudaFuncAttributeMaxDynamicSharedMemorySize, (int)smG);
    cudaFuncSetAttribute(drift_kernel,   cudaFuncAttributeMaxDynamicSharedMemorySize, (int)smF);

    cudaMemcpyAsync(z, z0, (size_t)BB * ZD * sizeof(float), cudaMemcpyDeviceToDevice);
    encoder_kernel<<<152, 128, smE>>>(x_ctx, y_ctx, mask, We1, be1, We2, be2, We3, be3);

    for (int s = 0; s < NSTEPS; ++s) {
        const float t = (float)s * DT;
        grad_kernel<<<304, 128, smG>>>(z, x_ctx, y_ctx, mask,
                                       Wd1, bd1, Wd2, bd2, Wd3, bd3, t);
        drift_kernel<<<152, 128, smF>>>(z, noises + (size_t)s * BB * ZD,
                                        Wf1, bf1, Wf2, bf2, Wf3, bf3, t);
    }
}

// round 4
// speedup vs baseline: 1.0004x; 1.0004x over previous
#include <cuda_runtime.h>

#define BB     2048
#define NCTX   64
#define ZD     64
#define RD     128
#define HD     128
#define NSTEPS 20
#define DT     0.05f
#define DIFF   0.3162277660168379f   /* sqrt(2*dt) */

// scratch (device globals: no allocations allowed)
__device__ float g_r[BB * RD];      // encoder output r
__device__ float g_grad[BB * ZD];   // clipped energy gradient per step

__device__ __forceinline__ float sigf(float x) { return 1.0f / (1.0f + __expf(-x)); }

// ---------------------------------------------------------------------------
// Encoder: r[b] = sum_n silu(silu([x,y]We1+b)We2+b)We3+b * m / max(sum m,1e-6)
// One block <-> strided b's. We2/We3 in SMEM (forward-only: stride 128 is
// conflict-free for fixed-k, varying-tid access). 4 context points / iter.
// ---------------------------------------------------------------------------
__global__ void __launch_bounds__(128, 1) encoder_kernel(
    const float* __restrict__ x_ctx, const float* __restrict__ y_ctx,
    const float* __restrict__ mask,
    const float* __restrict__ We1, const float* __restrict__ be1,
    const float* __restrict__ We2, const float* __restrict__ be2,
    const float* __restrict__ We3, const float* __restrict__ be3)
{
    extern __shared__ float sm[];
    float4* h1s  = (float4*)sm;           // 128 float4
    float4* h2s  = h1s + 128;             // 128 float4
    float*  We2s = (float*)(h2s + 128);   // 128*128
    float*  We3s = We2s + HD * HD;        // 128*128
    float*  xs   = We3s + HD * HD;        // 128
    float*  ys   = xs + 128;              // 64
    float*  ms   = ys + 64;               // 64

    const int tid = threadIdx.x;
    for (int i = tid; i < HD * HD; i += 128) { We2s[i] = We2[i]; We3s[i] = We3[i]; }
    const float w10 = We1[tid], w11 = We1[HD + tid], w12 = We1[2 * HD + tid];
    const float b1 = be1[tid], b2 = be2[tid], b3 = be3[tid];
    __syncthreads();

    for (int b = blockIdx.x; b < BB; b += gridDim.x) {
        xs[tid] = x_ctx[b * (NCTX * 2) + tid];
        if (tid < NCTX) { ys[tid] = y_ctx[b * NCTX + tid]; ms[tid] = mask[b * NCTX + tid]; }
        __syncthreads();

        float racc = 0.0f;
        #pragma unroll 1
        for (int it = 0; it < NCTX / 4; ++it) {
            const int n0 = it * 4;
            float4 h1;
            float* hp = (float*)&h1;
            #pragma unroll
            for (int q = 0; q < 4; ++q) {
                const int n = n0 + q;
                float p = b1 + xs[2 * n] * w10 + xs[2 * n + 1] * w11 + ys[n] * w12;
                hp[q] = p * sigf(p);
            }
            h1s[tid] = h1;
            __syncthreads();

            float a0 = b2, a1 = b2, a2 = b2, a3 = b2;
            #pragma unroll 8
            for (int k = 0; k < HD; ++k) {
                float4 hh = h1s[k];
                float  w  = We2s[k * HD + tid];
                a0 = fmaf(hh.x, w, a0); a1 = fmaf(hh.y, w, a1);
                a2 = fmaf(hh.z, w, a2); a3 = fmaf(hh.w, w, a3);
            }
            float4 h2;
            h2.x = a0 * sigf(a0); h2.y = a1 * sigf(a1);
            h2.z = a2 * sigf(a2); h2.w = a3 * sigf(a3);
            h2s[tid] = h2;
            __syncthreads();

            a0 = b3; a1 = b3; a2 = b3; a3 = b3;
            #pragma unroll 8
            for (int k = 0; k < HD; ++k) {
                float4 hh = h2s[k];
                float  w  = We3s[k * HD + tid];
                a0 = fmaf(hh.x, w, a0); a1 = fmaf(hh.y, w, a1);
                a2 = fmaf(hh.z, w, a2); a3 = fmaf(hh.w, w, a3);
            }
            racc = fmaf(a0, ms[n0 + 0], racc);
            racc = fmaf(a1, ms[n0 + 1], racc);
            racc = fmaf(a2, ms[n0 + 2], racc);
            racc = fmaf(a3, ms[n0 + 3], racc);
        }
        float msum = 0.0f;
        #pragma unroll
        for (int n = 0; n < NCTX; ++n) msum += ms[n];
        g_r[b * RD + tid] = racc / fmaxf(msum, 1e-6f);
        __syncthreads();
    }
}

// ---------------------------------------------------------------------------
// Energy-gradient kernel: g[b] = clip(z + t * d(u_lik)/dz, +-100).
// Decoder fwd+bwd over 64 ctx points, 4 per iteration.
// Wd1/Wd2 padded to stride 129 -> conflict-free for BOTH W (fwd, fixed k)
// and W^T (bwd, fixed col) access. dz deferred: accumulate sum_n dpre1 in
// registers, single W1^T matvec at the end. z-part of pre1 hoisted out of n.
// ---------------------------------------------------------------------------
__global__ void __launch_bounds__(128, 2) grad_kernel(
    const float* __restrict__ z, const float* __restrict__ x_ctx,
    const float* __restrict__ y_ctx, const float* __restrict__ mask,
    const float* __restrict__ Wd1, const float* __restrict__ bd1,
    const float* __restrict__ Wd2, const float* __restrict__ bd2,
    const float* __restrict__ Wd3, const float* __restrict__ bd3,
    float t)
{
    extern __shared__ float sm[];
    float4* h1s  = (float4*)sm;            // 128 float4 (h1 for 4 ctx pts)
    float4* dps  = h1s + 128;              // 128 float4 (dpre2 for 4 ctx pts)
    float4* wsum = dps + 128;              // 4 float4 (cross-warp reduce)
    float*  Wd1p = (float*)(wsum + 4);     // 66*129
    float*  Wd2p = Wd1p + 66 * 129;        // 128*129
    float*  xs   = Wd2p + 128 * 129;       // 128
    float*  ys   = xs + 128;               // 64
    float*  ms   = ys + 64;                // 64
    float*  zsh  = ms + 64;                // 64
    float*  ds   = zsh + 64;               // 128 (sum_n dpre1)

    const int tid = threadIdx.x;
    for (int i = tid; i < 66 * HD; i += 128) {
        int r = i >> 7, c = i & 127;
        Wd1p[r * 129 + c] = Wd1[i];
    }
    for (int i = tid; i < HD * HD; i += 128) {
        int r = i >> 7, c = i & 127;
        Wd2p[r * 129 + c] = Wd2[i];
    }
    const float b1 = bd1[tid], b2 = bd2[tid], w3 = Wd3[tid], bd3v = bd3[0];
    __syncthreads();
    const float wx0 = Wd1p[64 * 129 + tid];   // x-feature rows of Wd1
    const float wx1 = Wd1p[65 * 129 + tid];

    for (int b = blockIdx.x; b < BB; b += gridDim.x) {
        if (tid < ZD) zsh[tid] = z[b * ZD + tid];
        xs[tid] = x_ctx[b * (NCTX * 2) + tid];
        if (tid < NCTX) { ys[tid] = y_ctx[b * NCTX + tid]; ms[tid] = mask[b * NCTX + tid]; }
        __syncthreads();

        // n-invariant part of layer-1 preactivation (z contribution + bias)
        float pre1b = b1;
        #pragma unroll 8
        for (int k = 0; k < ZD; ++k) pre1b = fmaf(zsh[k], Wd1p[k * 129 + tid], pre1b);

        float dpsum = 0.0f;   // sum over n of dpre1[tid]
        if (t > 0.0f) {
            #pragma unroll 1
            for (int it = 0; it < NCTX / 4; ++it) {
                const int n0 = it * 4;
                float sd1[4];
                float4 h1;
                float* hp = (float*)&h1;
                #pragma unroll
                for (int q = 0; q < 4; ++q) {
                    const int n = n0 + q;
                    float p = fmaf(xs[2 * n], wx0, fmaf(xs[2 * n + 1], wx1, pre1b));
                    float s = sigf(p);
                    hp[q]  = p * s;
                    sd1[q] = s * (1.0f + p * (1.0f - s));   // silu'(pre1)
                }
                h1s[tid] = h1;
                __syncthreads();                              // A

                float a0 = b2, a1 = b2, a2 = b2, a3 = b2;
                #pragma unroll 8
                for (int k = 0; k < HD; ++k) {
                    float4 hh = h1s[k];
                    float  w  = Wd2p[k * 129 + tid];
                    a0 = fmaf(hh.x, w, a0); a1 = fmaf(hh.y, w, a1);
                    a2 = fmaf(hh.z, w, a2); a3 = fmaf(hh.w, w, a3);
                }
                const float s0 = sigf(a0), s1 = sigf(a1), s2 = sigf(a2), s3 = sigf(a3);
                float4 part;
                part.x = a0 * s0 * w3; part.y = a1 * s1 * w3;
                part.z = a2 * s2 * w3; part.w = a3 * s3 * w3;
                const float t0 = s0 * (1.0f + a0 * (1.0f - s0));  // silu'(pre2)
                const float t1 = s1 * (1.0f + a1 * (1.0f - s1));
                const float t2 = s2 * (1.0f + a2 * (1.0f - s2));
                const float t3 = s3 * (1.0f + a3 * (1.0f - s3));

                #pragma unroll
                for (int off = 16; off; off >>= 1) {
                    part.x += __shfl_xor_sync(0xffffffffu, part.x, off);
                    part.y += __shfl_xor_sync(0xffffffffu, part.y, off);
                    part.z += __shfl_xor_sync(0xffffffffu, part.z, off);
                    part.w += __shfl_xor_sync(0xffffffffu, part.w, off);
                }
                if ((tid & 31) == 0) wsum[tid >> 5] = part;
                __syncthreads();                              // B

                float4 r0 = wsum[0], r1 = wsum[1], r2 = wsum[2], r3 = wsum[3];
                const float out0 = r0.x + r1.x + r2.x + r3.x + bd3v;
                const float out1 = r0.y + r1.y + r2.y + r3.y + bd3v;
                const float out2 = r0.z + r1.z + r2.z + r3.z + bd3v;
                const float out3 = r0.w + r1.w + r2.w + r3.w + bd3v;
                // dU/d(out) = -t*(y-out)*m ; dpre2 = dU/dout * Wd3[j] * silu'(pre2)
                float4 dp;
                dp.x = -t * (ys[n0 + 0] - out0) * ms[n0 + 0] * w3 * t0;
                dp.y = -t * (ys[n0 + 1] - out1) * ms[n0 + 1] * w3 * t1;
                dp.z = -t * (ys[n0 + 2] - out2) * ms[n0 + 2] * w3 * t2;
                dp.w = -t * (ys[n0 + 3] - out3) * ms[n0 + 3] * w3 * t3;
                dps[tid] = dp;
                __syncthreads();                              // C

                float c0 = 0.0f, c1 = 0.0f, c2 = 0.0f, c3 = 0.0f;
                #pragma unroll 8
                for (int k = 0; k < HD; ++k) {
                    float4 dd = dps[k];
                    float  w  = Wd2p[tid * 129 + k];          // Wd2^T row, conflict-free
                    c0 = fmaf(dd.x, w, c0); c1 = fmaf(dd.y, w, c1);
                    c2 = fmaf(dd.z, w, c2); c3 = fmaf(dd.w, w, c3);
                }
                dpsum += c0 * sd1[0] + c1 * sd1[1] + c2 * sd1[2] + c3 * sd1[3];
            }
        }
        __syncthreads();
        ds[tid] = dpsum;
        __syncthreads();
        if (tid < ZD) {
            float acc = 0.0f;
            #pragma unroll 8
            for (int j = 0; j < HD; ++j) acc = fmaf(ds[j], Wd1p[tid * 129 + j], acc);
            float g = zsh[tid] + acc;                         // + u_prior grad (= z)
            g = fminf(fmaxf(g, -100.0f), 100.0f);
            g_grad[b * ZD + tid] = g;
        }
        __syncthreads();
    }
}

// ---------------------------------------------------------------------------
// Drift + z update: b = MLP([z, r, t]); z <- z + (b - g)*dt + diff*noise
// Drift weights (192 KB) in SMEM, one CTA/SM, ~14 b's per block.
// ---------------------------------------------------------------------------
__global__ void __launch_bounds__(128, 1) drift_kernel(
    float* __restrict__ z, const float* __restrict__ noise,
    const float* __restrict__ Wf1, const float* __restrict__ bf1,
    const float* __restrict__ Wf2, const float* __restrict__ bf2,
    const float* __restrict__ Wf3, const float* __restrict__ bf3,
    float t)
{
    extern __shared__ float sm[];
    float* Wf1s = sm;                      // 193*128
    float* Wf2s = Wf1s + 193 * HD;         // 128*128
    float* Wf3s = Wf2s + HD * HD;          // 128*64
    float* f1s  = Wf3s + HD * ZD;          // 128
    float* f2s  = f1s + 128;               // 128
    float* zsh  = f2s + 128;               // 64
    float* rsh  = zsh + 64;                // 128
    float* psum = rsh + 128;               // 128

    const int tid = threadIdx.x;
    for (int i = tid; i < 193 * HD; i += 128) Wf1s[i] = Wf1[i];
    for (int i = tid; i < HD * HD; i += 128)  Wf2s[i] = Wf2[i];
    for (int i = tid; i < HD * ZD; i += 128)  Wf3s[i] = Wf3[i];
    const float b1 = bf1[tid], b2 = bf2[tid];
    __syncthreads();
    const float wt = Wf1s[192 * HD + tid];

    for (int b = blockIdx.x; b < BB; b += gridDim.x) {
        if (tid < ZD) zsh[tid] = z[b * ZD + tid];
        rsh[tid] = g_r[b * RD + tid];
        __syncthreads();

        float p = fmaf(t, wt, b1);
        #pragma unroll 8
        for (int k = 0; k < ZD; ++k) p = fmaf(zsh[k], Wf1s[k * HD + tid], p);
        #pragma unroll 8
        for (int k = 0; k < RD; ++k) p = fmaf(rsh[k], Wf1s[(ZD + k) * HD + tid], p);
        f1s[tid] = p * sigf(p);
        __syncthreads();

        float p2 = b2;
        #pragma unroll 8
        for (int k = 0; k < HD; ++k) p2 = fmaf(f1s[k], Wf2s[k * HD + tid], p2);
        f2s[tid] = p2 * sigf(p2);
        __syncthreads();

        const int kk = tid & 63, half = tid >> 6;
        float acc = 0.0f;
        #pragma unroll 8
        for (int j = 0; j < 64; ++j)
            acc = fmaf(f2s[half * 64 + j], Wf3s[(half * 64 + j) * ZD + kk], acc);
        psum[tid] = acc;
        __syncthreads();

        if (tid < ZD) {
            const float bdrift = bf3[tid] + psum[tid] + psum[tid + 64];
            const float zn = zsh[tid] + (bdrift - g_grad[b * ZD + tid]) * DT
                           + DIFF * noise[b * ZD + tid];
            z[b * ZD + tid] = zn;
        }
        __syncthreads();
    }
}

// ---------------------------------------------------------------------------
extern "C" void kernel_launch(void* const* d_in, const int* in_sizes, int n_in,
                              void* d_out, int out_size)
{
    const float* x_ctx  = (const float*)d_in[0];
    const float* y_ctx  = (const float*)d_in[1];
    const float* mask   = (const float*)d_in[2];
    const float* z0     = (const float*)d_in[3];
    const float* noises = (const float*)d_in[4];
    const float* We1 = (const float*)d_in[5];  const float* be1 = (const float*)d_in[6];
    const float* We2 = (const float*)d_in[7];  const float* be2 = (const float*)d_in[8];
    const float* We3 = (const float*)d_in[9];  const float* be3 = (const float*)d_in[10];
    const float* Wd1 = (const float*)d_in[11]; const float* bd1 = (const float*)d_in[12];
    const float* Wd2 = (const float*)d_in[13]; const float* bd2 = (const float*)d_in[14];
    const float* Wd3 = (const float*)d_in[15]; const float* bd3 = (const float*)d_in[16];
    const float* Wf1 = (const float*)d_in[17]; const float* bf1 = (const float*)d_in[18];
    const float* Wf2 = (const float*)d_in[19]; const float* bf2 = (const float*)d_in[20];
    const float* Wf3 = (const float*)d_in[21]; const float* bf3 = (const float*)d_in[22];
    float* z = (float*)d_out;   // z buffer lives in d_out; final state is the answer

    const size_t smE = (size_t)(512 + 512 + 16384 + 16384 + 128 + 64 + 64) * 4;
    const size_t smG = (size_t)(512 + 512 + 16 + 66 * 129 + 128 * 129
                                + 128 + 64 + 64 + 64 + 128) * 4;
    const size_t smF = (size_t)(193 * 128 + 128 * 128 + 128 * 64
                                + 128 + 128 + 64 + 128 + 128) * 4;

    cudaFuncSetAttribute(encoder_kernel, cudaFuncAttributeMaxDynamicSharedMemorySize, (int)smE);
    cudaFuncSetAttribute(grad_kernel,    cudaFuncAttributeMaxDynamicSharedMemorySize, (int)smG);
    cudaFuncSetAttribute(drift_kernel,   cudaFuncAttributeMaxDynamicSharedMemorySize, (int)smF);

    cudaMemcpyAsync(z, z0, (size_t)BB * ZD * sizeof(float), cudaMemcpyDeviceToDevice);
    encoder_kernel<<<152, 128, smE>>>(x_ctx, y_ctx, mask, We1, be1, We2, be2, We3, be3);

    for (int s = 0; s < NSTEPS; ++s) {
        const float t = (float)s * DT;
        grad_kernel<<<304, 128, smG>>>(z, x_ctx, y_ctx, mask,
                                       Wd1, bd1, Wd2, bd2, Wd3, bd3, t);
        drift_kernel<<<152, 128, smF>>>(z, noises + (size_t)s * BB * ZD,
                                        Wf1, bf1, Wf2, bf2, Wf3, bf3, t);
    }
}

// round 7
// speedup vs baseline: 1.2771x; 1.2767x over previous
#include <cuda_runtime.h>

#define BB     2048
#define NCTX   64
#define ZD     64
#define RD     128
#define HD     128
#define NSTEPS 20
#define DT     0.05f
#define DIFF   0.3162277660168379f   /* sqrt(2*dt) */

typedef unsigned long long u64;

// scratch (device globals: no allocations allowed)
__device__ float g_r[BB * RD];      // encoder output r
__device__ float g_grad[BB * ZD];   // clipped energy gradient per step

__device__ __forceinline__ float sigf(float x) { return 1.0f / (1.0f + __expf(-x)); }

__device__ __forceinline__ u64 pk2(float x, float y) {
    u64 r; asm("mov.b64 %0, {%1, %2};" : "=l"(r) : "f"(x), "f"(y)); return r;
}
__device__ __forceinline__ void up2(u64 v, float& x, float& y) {
    asm("mov.b64 {%0, %1}, %2;" : "=f"(x), "=f"(y) : "l"(v));
}
__device__ __forceinline__ void fma2(u64& d, u64 a, u64 b) {
    asm("fma.rn.f32x2 %0, %1, %2, %0;" : "+l"(d) : "l"(a), "l"(b));
}
__device__ __forceinline__ void gbar(int id) {
    asm volatile("bar.sync %0, 128;" :: "r"(id) : "memory");
}

// ---------------------------------------------------------------------------
// Encoder (runs once): r[b] = masked-mean over n of 3-layer set MLP.
// ---------------------------------------------------------------------------
__global__ void __launch_bounds__(128, 1) encoder_kernel(
    const float* __restrict__ x_ctx, const float* __restrict__ y_ctx,
    const float* __restrict__ mask,
    const float* __restrict__ We1, const float* __restrict__ be1,
    const float* __restrict__ We2, const float* __restrict__ be2,
    const float* __restrict__ We3, const float* __restrict__ be3)
{
    extern __shared__ float sm[];
    float4* h1s  = (float4*)sm;           // 128 float4
    float4* h2s  = h1s + 128;             // 128 float4
    float*  We2s = (float*)(h2s + 128);   // 128*128
    float*  We3s = We2s + HD * HD;        // 128*128
    float*  xs   = We3s + HD * HD;        // 128
    float*  ys   = xs + 128;              // 64
    float*  ms   = ys + 64;               // 64

    const int tid = threadIdx.x;
    for (int i = tid; i < HD * HD; i += 128) { We2s[i] = We2[i]; We3s[i] = We3[i]; }
    const float w10 = We1[tid], w11 = We1[HD + tid], w12 = We1[2 * HD + tid];
    const float b1 = be1[tid], b2 = be2[tid], b3 = be3[tid];
    __syncthreads();

    for (int b = blockIdx.x; b < BB; b += gridDim.x) {
        xs[tid] = x_ctx[b * (NCTX * 2) + tid];
        if (tid < NCTX) { ys[tid] = y_ctx[b * NCTX + tid]; ms[tid] = mask[b * NCTX + tid]; }
        __syncthreads();

        float racc = 0.0f;
        #pragma unroll 1
        for (int it = 0; it < NCTX / 4; ++it) {
            const int n0 = it * 4;
            float4 h1;
            float* hp = (float*)&h1;
            #pragma unroll
            for (int q = 0; q < 4; ++q) {
                const int n = n0 + q;
                float p = b1 + xs[2 * n] * w10 + xs[2 * n + 1] * w11 + ys[n] * w12;
                hp[q] = p * sigf(p);
            }
            h1s[tid] = h1;
            __syncthreads();

            float a0 = b2, a1 = b2, a2 = b2, a3 = b2;
            #pragma unroll 8
            for (int k = 0; k < HD; ++k) {
                float4 hh = h1s[k];
                float  w  = We2s[k * HD + tid];
                a0 = fmaf(hh.x, w, a0); a1 = fmaf(hh.y, w, a1);
                a2 = fmaf(hh.z, w, a2); a3 = fmaf(hh.w, w, a3);
            }
            float4 h2;
            h2.x = a0 * sigf(a0); h2.y = a1 * sigf(a1);
            h2.z = a2 * sigf(a2); h2.w = a3 * sigf(a3);
            h2s[tid] = h2;
            __syncthreads();

            a0 = b3; a1 = b3; a2 = b3; a3 = b3;
            #pragma unroll 8
            for (int k = 0; k < HD; ++k) {
                float4 hh = h2s[k];
                float  w  = We3s[k * HD + tid];
                a0 = fmaf(hh.x, w, a0); a1 = fmaf(hh.y, w, a1);
                a2 = fmaf(hh.z, w, a2); a3 = fmaf(hh.w, w, a3);
            }
            racc = fmaf(a0, ms[n0 + 0], racc);
            racc = fmaf(a1, ms[n0 + 1], racc);
            racc = fmaf(a2, ms[n0 + 2], racc);
            racc = fmaf(a3, ms[n0 + 3], racc);
        }
        float msum = 0.0f;
        #pragma unroll
        for (int n = 0; n < NCTX; ++n) msum += ms[n];
        g_r[b * RD + tid] = racc / fmaxf(msum, 1e-6f);
        __syncthreads();
    }
}

// ---------------------------------------------------------------------------
// Energy-gradient kernel. 512 threads = 4 independent 128-thread groups
// sharing ONE SMEM weight copy (named barriers). 16 ctx points per inner
// iteration, f32x2 packed FMA accumulation. Stride-129 weight padding keeps
// both W (fwd) and W^T (bwd) accesses conflict-free. Group scratch base is
// padded to a 16-byte boundary (float4 stores!).
// ---------------------------------------------------------------------------
#define GPB   4            /* groups per block            */
#define GSZ   3072         /* floats of SMEM per group (16B multiple) */
#define WPAD  2            /* pad so gbase is 16B aligned: 25026+2 = 25028 */

__global__ void __launch_bounds__(512, 1) grad_kernel(
    const float* __restrict__ z, const float* __restrict__ x_ctx,
    const float* __restrict__ y_ctx, const float* __restrict__ mask,
    const float* __restrict__ Wd1, const float* __restrict__ bd1,
    const float* __restrict__ Wd2, const float* __restrict__ bd2,
    const float* __restrict__ Wd3, const float* __restrict__ bd3,
    float t)
{
    extern __shared__ float sm[];
    float* Wd1p = sm;                     // 66*129  = 8514
    float* Wd2p = Wd1p + 66 * 129;        // 128*129 = 16512
    float* gbase = Wd2p + 128 * 129 + WPAD; // 16B-aligned

    const int tidb = threadIdx.x;
    const int grp  = tidb >> 7;
    const int tid  = tidb & 127;
    const int bar  = grp + 1;

    float*  gb   = gbase + grp * GSZ;
    float4* h1s  = (float4*)gb;           // 128 rows * 5 float4 (pad) = 2560 f
    float*  wsum = gb + 2560;             // 4 warps * 16 = 64
    float*  xs   = wsum + 64;             // 128
    float*  ys   = xs + 128;              // 64
    float*  ms   = ys + 64;               // 64
    float*  zsh  = ms + 64;               // 64
    float*  ds   = zsh + 64;              // 128

    for (int i = tidb; i < 66 * HD; i += 512) {
        int r = i >> 7, c = i & 127;
        Wd1p[r * 129 + c] = Wd1[i];
    }
    for (int i = tidb; i < HD * HD; i += 512) {
        int r = i >> 7, c = i & 127;
        Wd2p[r * 129 + c] = Wd2[i];
    }
    const float b1 = bd1[tid], b2 = bd2[tid], w3 = Wd3[tid], bd3v = bd3[0];
    __syncthreads();
    const float wx0 = Wd1p[64 * 129 + tid];
    const float wx1 = Wd1p[65 * 129 + tid];
    const int   warp = tid >> 5;

    for (int b = blockIdx.x * GPB + grp; b < BB; b += gridDim.x * GPB) {
        if (tid < ZD) zsh[tid] = z[b * ZD + tid];
        xs[tid] = x_ctx[b * (NCTX * 2) + tid];
        if (tid < NCTX) { ys[tid] = y_ctx[b * NCTX + tid]; ms[tid] = mask[b * NCTX + tid]; }
        gbar(bar);

        float pre1b = b1;
        #pragma unroll 8
        for (int k = 0; k < ZD; ++k) pre1b = fmaf(zsh[k], Wd1p[k * 129 + tid], pre1b);

        float dpsum = 0.0f;
        if (t > 0.0f) {
            #pragma unroll 1
            for (int it = 0; it < NCTX / 16; ++it) {
                const int n0 = it * 16;
                float sd1[16];
                float4 h1v[4];
                float* hp = (float*)h1v;
                #pragma unroll
                for (int q = 0; q < 16; ++q) {
                    const int n = n0 + q;
                    float p = fmaf(xs[2 * n], wx0, fmaf(xs[2 * n + 1], wx1, pre1b));
                    float s = sigf(p);
                    hp[q]  = p * s;
                    sd1[q] = s * (1.0f + p * (1.0f - s));
                }
                #pragma unroll
                for (int c = 0; c < 4; ++c) h1s[tid * 5 + c] = h1v[c];
                gbar(bar);                                    // A

                u64 acc[8];
                const u64 bb2 = pk2(b2, b2);
                #pragma unroll
                for (int i = 0; i < 8; ++i) acc[i] = bb2;
                #pragma unroll 4
                for (int k = 0; k < HD; ++k) {
                    const float w  = Wd2p[k * 129 + tid];
                    const u64   w2 = pk2(w, w);
                    const float4 A0 = h1s[k * 5 + 0];
                    const float4 A1 = h1s[k * 5 + 1];
                    const float4 A2 = h1s[k * 5 + 2];
                    const float4 A3 = h1s[k * 5 + 3];
                    fma2(acc[0], w2, pk2(A0.x, A0.y)); fma2(acc[1], w2, pk2(A0.z, A0.w));
                    fma2(acc[2], w2, pk2(A1.x, A1.y)); fma2(acc[3], w2, pk2(A1.z, A1.w));
                    fma2(acc[4], w2, pk2(A2.x, A2.y)); fma2(acc[5], w2, pk2(A2.z, A2.w));
                    fma2(acc[6], w2, pk2(A3.x, A3.y)); fma2(acc[7], w2, pk2(A3.z, A3.w));
                }
                float a[16];
                #pragma unroll
                for (int i = 0; i < 8; ++i) up2(acc[i], a[2 * i], a[2 * i + 1]);

                float part[16], tder[16];
                #pragma unroll
                for (int q = 0; q < 16; ++q) {
                    const float s = sigf(a[q]);
                    part[q] = a[q] * s * w3;
                    tder[q] = s * (1.0f + a[q] * (1.0f - s));
                }
                #pragma unroll
                for (int off = 16; off; off >>= 1) {
                    #pragma unroll
                    for (int q = 0; q < 16; ++q)
                        part[q] += __shfl_xor_sync(0xffffffffu, part[q], off);
                }
                if ((tid & 31) == 0) {
                    float4* w4 = (float4*)wsum;
                    #pragma unroll
                    for (int c = 0; c < 4; ++c)
                        w4[warp * 4 + c] = make_float4(part[4 * c], part[4 * c + 1],
                                                       part[4 * c + 2], part[4 * c + 3]);
                }
                gbar(bar);                                    // B

                float out[16];
                {
                    const float4* w4 = (const float4*)wsum;
                    #pragma unroll
                    for (int c = 0; c < 4; ++c) {
                        float4 s0 = w4[c], s1 = w4[4 + c], s2 = w4[8 + c], s3 = w4[12 + c];
                        out[4 * c + 0] = s0.x + s1.x + s2.x + s3.x + bd3v;
                        out[4 * c + 1] = s0.y + s1.y + s2.y + s3.y + bd3v;
                        out[4 * c + 2] = s0.z + s1.z + s2.z + s3.z + bd3v;
                        out[4 * c + 3] = s0.w + s1.w + s2.w + s3.w + bd3v;
                    }
                }
                float4 dpv[4];
                float* dpp = (float*)dpv;
                #pragma unroll
                for (int q = 0; q < 16; ++q) {
                    const int n = n0 + q;
                    dpp[q] = -t * (ys[n] - out[q]) * ms[n] * w3 * tder[q];
                }
                #pragma unroll
                for (int c = 0; c < 4; ++c) h1s[tid * 5 + c] = dpv[c];   // reuse buf
                gbar(bar);                                    // C

                u64 cac[8];
                #pragma unroll
                for (int i = 0; i < 8; ++i) cac[i] = 0ull;
                #pragma unroll 4
                for (int k = 0; k < HD; ++k) {
                    const float w  = Wd2p[tid * 129 + k];     // W2^T, conflict-free
                    const u64   w2 = pk2(w, w);
                    const float4 D0 = h1s[k * 5 + 0];
                    const float4 D1 = h1s[k * 5 + 1];
                    const float4 D2 = h1s[k * 5 + 2];
                    const float4 D3 = h1s[k * 5 + 3];
                    fma2(cac[0], w2, pk2(D0.x, D0.y)); fma2(cac[1], w2, pk2(D0.z, D0.w));
                    fma2(cac[2], w2, pk2(D1.x, D1.y)); fma2(cac[3], w2, pk2(D1.z, D1.w));
                    fma2(cac[4], w2, pk2(D2.x, D2.y)); fma2(cac[5], w2, pk2(D2.z, D2.w));
                    fma2(cac[6], w2, pk2(D3.x, D3.y)); fma2(cac[7], w2, pk2(D3.z, D3.w));
                }
                #pragma unroll
                for (int i = 0; i < 8; ++i) {
                    float c0, c1;
                    up2(cac[i], c0, c1);
                    dpsum = fmaf(c0, sd1[2 * i], dpsum);
                    dpsum = fmaf(c1, sd1[2 * i + 1], dpsum);
                }
                gbar(bar);                                    // D (h1s reuse next iter)
            }
        }
        ds[tid] = dpsum;
        gbar(bar);
        if (tid < ZD) {
            float acc = 0.0f;
            #pragma unroll 8
            for (int j = 0; j < HD; ++j) acc = fmaf(ds[j], Wd1p[tid * 129 + j], acc);
            float g = zsh[tid] + acc;
            g = fminf(fmaxf(g, -100.0f), 100.0f);
            g_grad[b * ZD + tid] = g;
        }
        gbar(bar);
    }
}

// ---------------------------------------------------------------------------
// Drift + z update, 4 batch elements per iteration (float4 broadcasts).
// ---------------------------------------------------------------------------
__global__ void __launch_bounds__(128, 1) drift_kernel(
    float* __restrict__ z, const float* __restrict__ noise,
    const float* __restrict__ Wf1, const float* __restrict__ bf1,
    const float* __restrict__ Wf2, const float* __restrict__ bf2,
    const float* __restrict__ Wf3, const float* __restrict__ bf3,
    float t)
{
    extern __shared__ float sm[];
    float*  Wf1s = sm;                       // 193*128 = 24704
    float*  Wf2s = Wf1s + 193 * HD;          // 16384
    float*  Wf3s = Wf2s + HD * HD;           // 8192
    float4* f1sT = (float4*)(Wf3s + HD * ZD); // 128 f4 (offset 49280 f, 16B ok)
    float4* f2sT = f1sT + 128;               // 128 f4
    float4* zshT = f2sT + 128;               // 64 f4
    float4* rshT = zshT + 64;                // 128 f4

    const int tid = threadIdx.x;
    for (int i = tid; i < 193 * HD; i += 128) Wf1s[i] = Wf1[i];
    for (int i = tid; i < HD * HD; i += 128)  Wf2s[i] = Wf2[i];
    for (int i = tid; i < HD * ZD; i += 128)  Wf3s[i] = Wf3[i];
    const float b1 = bf1[tid], b2 = bf2[tid];
    const float bf3v = bf3[tid & 63];
    __syncthreads();
    const float wt = Wf1s[192 * HD + tid];
    const int kk = tid & 63, g2 = tid >> 6;

    for (int b0 = blockIdx.x * 4; b0 < BB; b0 += gridDim.x * 4) {
        float* zf = (float*)zshT;
        float* rf = (float*)rshT;
        #pragma unroll
        for (int i = tid; i < 4 * ZD; i += 128) {
            int q = i >> 6, k = i & 63;
            zf[k * 4 + q] = z[(b0 + q) * ZD + k];
        }
        #pragma unroll
        for (int i = tid; i < 4 * RD; i += 128) {
            int q = i >> 7, k = i & 127;
            rf[k * 4 + q] = g_r[(b0 + q) * RD + k];
        }
        __syncthreads();

        const float pb = fmaf(t, wt, b1);
        float p0 = pb, p1 = pb, p2 = pb, p3 = pb;
        #pragma unroll 8
        for (int k = 0; k < ZD; ++k) {
            const float w = Wf1s[k * HD + tid];
            const float4 v = zshT[k];
            p0 = fmaf(v.x, w, p0); p1 = fmaf(v.y, w, p1);
            p2 = fmaf(v.z, w, p2); p3 = fmaf(v.w, w, p3);
        }
        #pragma unroll 8
        for (int k = 0; k < RD; ++k) {
            const float w = Wf1s[(ZD + k) * HD + tid];
            const float4 v = rshT[k];
            p0 = fmaf(v.x, w, p0); p1 = fmaf(v.y, w, p1);
            p2 = fmaf(v.z, w, p2); p3 = fmaf(v.w, w, p3);
        }
        f1sT[tid] = make_float4(p0 * sigf(p0), p1 * sigf(p1), p2 * sigf(p2), p3 * sigf(p3));
        __syncthreads();

        p0 = b2; p1 = b2; p2 = b2; p3 = b2;
        #pragma unroll 8
        for (int k = 0; k < HD; ++k) {
            const float w = Wf2s[k * HD + tid];
            const float4 v = f1sT[k];
            p0 = fmaf(v.x, w, p0); p1 = fmaf(v.y, w, p1);
            p2 = fmaf(v.z, w, p2); p3 = fmaf(v.w, w, p3);
        }
        f2sT[tid] = make_float4(p0 * sigf(p0), p1 * sigf(p1), p2 * sigf(p2), p3 * sigf(p3));
        __syncthreads();

        // layer 3: thread covers (kk, q=g2) and (kk, q=g2+2)
        float accA = 0.0f, accB = 0.0f;
        #pragma unroll 8
        for (int j = 0; j < HD; ++j) {
            const float w = Wf3s[j * ZD + kk];
            const float4 v = f2sT[j];
            const float vA = g2 ? v.y : v.x;
            const float vB = g2 ? v.w : v.z;
            accA = fmaf(vA, w, accA);
            accB = fmaf(vB, w, accB);
        }
        {
            const int qA = g2, qB = g2 + 2;
            const int bA = b0 + qA, bB = b0 + qB;
            const float znA = zf[kk * 4 + qA]
                + (bf3v + accA - g_grad[bA * ZD + kk]) * DT
                + DIFF * noise[bA * ZD + kk];
            const float znB = zf[kk * 4 + qB]
                + (bf3v + accB - g_grad[bB * ZD + kk]) * DT
                + DIFF * noise[bB * ZD + kk];
            z[bA * ZD + kk] = znA;
            z[bB * ZD + kk] = znB;
        }
        __syncthreads();
    }
}

// ---------------------------------------------------------------------------
extern "C" void kernel_launch(void* const* d_in, const int* in_sizes, int n_in,
                              void* d_out, int out_size)
{
    const float* x_ctx  = (const float*)d_in[0];
    const float* y_ctx  = (const float*)d_in[1];
    const float* mask   = (const float*)d_in[2];
    const float* z0     = (const float*)d_in[3];
    const float* noises = (const float*)d_in[4];
    const float* We1 = (const float*)d_in[5];  const float* be1 = (const float*)d_in[6];
    const float* We2 = (const float*)d_in[7];  const float* be2 = (const float*)d_in[8];
    const float* We3 = (const float*)d_in[9];  const float* be3 = (const float*)d_in[10];
    const float* Wd1 = (const float*)d_in[11]; const float* bd1 = (const float*)d_in[12];
    const float* Wd2 = (const float*)d_in[13]; const float* bd2 = (const float*)d_in[14];
    const float* Wd3 = (const float*)d_in[15]; const float* bd3 = (const float*)d_in[16];
    const float* Wf1 = (const float*)d_in[17]; const float* bf1 = (const float*)d_in[18];
    const float* Wf2 = (const float*)d_in[19]; const float* bf2 = (const float*)d_in[20];
    const float* Wf3 = (const float*)d_in[21]; const float* bf3 = (const float*)d_in[22];
    float* z = (float*)d_out;   // z buffer lives in d_out; final state is the answer

    const size_t smE = (size_t)(512 + 512 + 16384 + 16384 + 128 + 64 + 64) * 4;
    const size_t smG = (size_t)(66 * 129 + 128 * 129 + WPAD + GPB * GSZ) * 4;
    const size_t smF = (size_t)(193 * 128 + 128 * 128 + 128 * 64
                                + 512 + 512 + 256 + 512) * 4;

    cudaFuncSetAttribute(encoder_kernel, cudaFuncAttributeMaxDynamicSharedMemorySize, (int)smE);
    cudaFuncSetAttribute(grad_kernel,    cudaFuncAttributeMaxDynamicSharedMemorySize, (int)smG);
    cudaFuncSetAttribute(drift_kernel,   cudaFuncAttributeMaxDynamicSharedMemorySize, (int)smF);

    cudaMemcpyAsync(z, z0, (size_t)BB * ZD * sizeof(float), cudaMemcpyDeviceToDevice);
    encoder_kernel<<<148, 128, smE>>>(x_ctx, y_ctx, mask, We1, be1, We2, be2, We3, be3);

    for (int s = 0; s < NSTEPS; ++s) {
        const float t = (float)s * DT;
        grad_kernel<<<148, 512, smG>>>(z, x_ctx, y_ctx, mask,
                                       Wd1, bd1, Wd2, bd2, Wd3, bd3, t);
        drift_kernel<<<148, 128, smF>>>(z, noises + (size_t)s * BB * ZD,
                                        Wf1, bf1, Wf2, bf2, Wf3, bf3, t);
    }
}